// round 1
// baseline (speedup 1.0000x reference)
#include <cuda_runtime.h>

// CausalConv1d (depthwise, K=4) + SiLU
// x: (B=4, S=8192, D=2048) fp32, w: (D, 1, K=4) fp32, out: (B, S, D) fp32
// y[b,s,d] = silu( sum_{k=0..3} x[b, s-3+k, d] * w[d,0,k] )  (x padded left with zeros)

constexpr int B_ = 4;
constexpr int S_ = 8192;
constexpr int D_ = 2048;
constexpr int D4 = D_ / 4;      // 512 float4 lanes along channel dim
constexpr int T_ = 8;           // s-positions per thread (sliding window)
constexpr int THREADS = 128;

__device__ __forceinline__ float silu_f(float v) {
    return v / (1.0f + __expf(-v));
}

__global__ __launch_bounds__(THREADS)
void causal_conv1d_silu_kernel(const float4* __restrict__ x,
                               const float4* __restrict__ w4,   // w viewed as [D] float4 (4 taps per channel)
                               float4* __restrict__ y)
{
    const int d4 = blockIdx.x * THREADS + threadIdx.x;   // which float4 channel group
    const int s0 = blockIdx.y * T_;                      // first s this thread produces
    const int b  = blockIdx.z;

    // Taps for the 4 channels in this float4 lane.
    // w layout: w[c][0][k] at linear index c*4 + k  ->  w4[c] = (k0,k1,k2,k3) for channel c.
    const int c0 = d4 * 4;
    const float4 wA = __ldg(&w4[c0 + 0]);
    const float4 wB = __ldg(&w4[c0 + 1]);
    const float4 wC = __ldg(&w4[c0 + 2]);
    const float4 wD = __ldg(&w4[c0 + 3]);

    const int rowbase = (b * S_) * D4 + d4;  // float4 index of (b, s=0, d4)

    // Sliding window: x at s-3, s-2, s-1 (zero for s<0 — only happens in the first s-block)
    float4 xm3, xm2, xm1;
    if (s0 >= 3) {
        xm3 = x[rowbase + (s0 - 3) * D4];
        xm2 = x[rowbase + (s0 - 2) * D4];
        xm1 = x[rowbase + (s0 - 1) * D4];
    } else {
        const float4 z = make_float4(0.f, 0.f, 0.f, 0.f);
        xm3 = (s0 - 3 >= 0) ? x[rowbase + (s0 - 3) * D4] : z;
        xm2 = (s0 - 2 >= 0) ? x[rowbase + (s0 - 2) * D4] : z;
        xm1 = (s0 - 1 >= 0) ? x[rowbase + (s0 - 1) * D4] : z;
    }

    const int base = rowbase + s0 * D4;

#pragma unroll
    for (int t = 0; t < T_; ++t) {
        const float4 xc = x[base + t * D4];

        float4 o;
        o.x = fmaf(xm3.x, wA.x, fmaf(xm2.x, wA.y, fmaf(xm1.x, wA.z, xc.x * wA.w)));
        o.y = fmaf(xm3.y, wB.x, fmaf(xm2.y, wB.y, fmaf(xm1.y, wB.z, xc.y * wB.w)));
        o.z = fmaf(xm3.z, wC.x, fmaf(xm2.z, wC.y, fmaf(xm1.z, wC.z, xc.z * wC.w)));
        o.w = fmaf(xm3.w, wD.x, fmaf(xm2.w, wD.y, fmaf(xm1.w, wD.z, xc.w * wD.w)));

        o.x = silu_f(o.x);
        o.y = silu_f(o.y);
        o.z = silu_f(o.z);
        o.w = silu_f(o.w);

        y[base + t * D4] = o;

        xm3 = xm2; xm2 = xm1; xm1 = xc;
    }
}

extern "C" void kernel_launch(void* const* d_in, const int* in_sizes, int n_in,
                              void* d_out, int out_size)
{
    const float4* x  = (const float4*)d_in[0];
    const float4* w4 = (const float4*)d_in[1];   // (D,1,4) fp32 == D contiguous float4
    float4* y = (float4*)d_out;

    dim3 block(THREADS, 1, 1);
    dim3 grid(D4 / THREADS, S_ / T_, B_);   // (4, 1024, 4)
    causal_conv1d_silu_kernel<<<grid, block>>>(x, w4, y);
}

// round 2
// speedup vs baseline: 1.2271x; 1.2271x over previous
#include <cuda_runtime.h>

// CausalConv1d (depthwise, K=4) + SiLU
// x: (B=4, S=8192, D=2048) fp32, w: (D, 1, 4) fp32, out: (B, S, D) fp32
// y[b,s,d] = silu( sum_{k=0..3} x[b, s-3+k, d] * w[d,0,k] )   (causal left zero-pad)

constexpr int B_ = 4;
constexpr int S_ = 8192;
constexpr int D_ = 2048;
constexpr int D4 = D_ / 4;      // 512 float4 lanes along channel dim
constexpr int T_ = 8;           // s-positions per thread
constexpr int THREADS = 128;

// silu(v) = v * sigmoid(v) = h + h*tanh(h),  h = v/2.  One MUFU op.
__device__ __forceinline__ float silu_f(float v) {
    float h = 0.5f * v;
    float t;
    asm("tanh.approx.f32 %0, %1;" : "=f"(t) : "f"(h));
    return fmaf(h, t, h);
}

__global__ __launch_bounds__(THREADS, 7)
void causal_conv1d_silu_kernel(const float4* __restrict__ x,
                               const float4* __restrict__ w4,   // [D] float4: 4 taps per channel
                               float4* __restrict__ y)
{
    const int d4 = blockIdx.x * THREADS + threadIdx.x;   // float4 channel group
    const int s0 = blockIdx.y * T_;
    const int b  = blockIdx.z;

    const int base = (b * S_ + s0) * D4 + d4;            // float4 index of (b, s0, d4)

    // ---- Front-batched loads: 11 independent LDG.128 (high MLP) ----
    float4 r[T_ + 3];
    if (blockIdx.y != 0) {
        r[0] = x[base - 3 * D4];
        r[1] = x[base - 2 * D4];
        r[2] = x[base - 1 * D4];
    } else {
        const float4 z = make_float4(0.f, 0.f, 0.f, 0.f);
        r[0] = z; r[1] = z; r[2] = z;
    }
#pragma unroll
    for (int t = 0; t < T_; ++t)
        r[t + 3] = x[base + t * D4];

    // Taps for the 4 channels in this lane: w4[c] = (k0,k1,k2,k3) of channel c.
    const int c0 = d4 * 4;
    const float4 wA = __ldg(&w4[c0 + 0]);
    const float4 wB = __ldg(&w4[c0 + 1]);
    const float4 wC = __ldg(&w4[c0 + 2]);
    const float4 wD = __ldg(&w4[c0 + 3]);

#pragma unroll
    for (int t = 0; t < T_; ++t) {
        float4 o;
        o.x = fmaf(r[t].x, wA.x, fmaf(r[t+1].x, wA.y, fmaf(r[t+2].x, wA.z, r[t+3].x * wA.w)));
        o.y = fmaf(r[t].y, wB.x, fmaf(r[t+1].y, wB.y, fmaf(r[t+2].y, wB.z, r[t+3].y * wB.w)));
        o.z = fmaf(r[t].z, wC.x, fmaf(r[t+1].z, wC.y, fmaf(r[t+2].z, wC.z, r[t+3].z * wC.w)));
        o.w = fmaf(r[t].w, wD.x, fmaf(r[t+1].w, wD.y, fmaf(r[t+2].w, wD.z, r[t+3].w * wD.w)));

        o.x = silu_f(o.x);
        o.y = silu_f(o.y);
        o.z = silu_f(o.z);
        o.w = silu_f(o.w);

        // Streaming store: output is never re-read — keep L2 for x halos.
        __stcs(&y[base + t * D4], o);
    }
}

extern "C" void kernel_launch(void* const* d_in, const int* in_sizes, int n_in,
                              void* d_out, int out_size)
{
    const float4* x  = (const float4*)d_in[0];
    const float4* w4 = (const float4*)d_in[1];
    float4* y = (float4*)d_out;

    dim3 block(THREADS, 1, 1);
    dim3 grid(D4 / THREADS, S_ / T_, B_);   // (4, 1024, 4)
    causal_conv1d_silu_kernel<<<grid, block>>>(x, w4, y);
}